// round 5
// baseline (speedup 1.0000x reference)
#include <cuda_runtime.h>
#include <cuda_bf16.h>

#define NX 192
#define NY 192
#define NZ 192
#define NXY (NX * NY)

#define VEC 4                    // floats per thread in x (float4)
#define XLANES 16                // lanes spanning x  -> 64 x per warp
#define YSPW 2                   // y rows per warp (lane bit 4)
#define WYD 4                    // warps per block -> 8 y rows per block
#define NTHREADS 128
#define SEGW (XLANES * VEC)      // 64
#define ZCHUNK 24                // divisible by 3 (register rotation)
#define GXB (NX / SEGW)          // 3
#define GYB (NY / (WYD * YSPW))  // 24
#define GZB (NZ / ZCHUNK)        // 8
#define NBLOCKS (GXB * GYB * GZB) // 576

#define FULLMASK 0xFFFFFFFFu

__device__ double g_acc = 0.0;
__device__ unsigned int g_done = 0;

// One image row: load a float4 quad, fetch x-neighbors (shuffle inside the
// 16-lane x-group; predicated scalar LDG at segment edges), emit per-element
//   h[c] = v(x-1)+v(x)+v(x+1)   (x 3-box)
//   d[c] = v(x+1)-v(x-1)        (x central diff)
__device__ __forceinline__ void row_pass(const float* __restrict__ row,
                                         int x4, int xq, int seg,
                                         float* __restrict__ h,
                                         float* __restrict__ d)
{
    float4 v4 = *reinterpret_cast<const float4*>(row + x4);
    float v0 = v4.x, v1 = v4.y, v2 = v4.z, v3 = v4.w;
    float l = __shfl_up_sync(FULLMASK, v3, 1, XLANES);
    float r = __shfl_down_sync(FULLMASK, v0, 1, XLANES);
    if (xq == 0)          l = (seg == 0)       ? v0 : row[x4 - 1];
    if (xq == XLANES - 1) r = (seg == GXB - 1) ? v3 : row[x4 + VEC];
    h[0] = l  + v0 + v1;  d[0] = v1 - l;
    h[1] = v0 + v1 + v2;  d[1] = v2 - v0;
    h[2] = v1 + v2 + v3;  d[2] = v3 - v1;
    h[3] = v2 + v3 + r;   d[3] = r  - v2;
}

// Per-plane 2D stats for this thread's 4 output voxels:
//   gx = sum_{dy} d, gy = h(y+1)-h(y-1), b = 3x3 box sum
__device__ __forceinline__ void plane_pass(const float* __restrict__ plane,
                                           const int* __restrict__ rowoff,
                                           int x4, int xq, int seg,
                                           float* __restrict__ gx,
                                           float* __restrict__ gy,
                                           float* __restrict__ b)
{
    float h0[VEC], h[VEC], d[VEC];
    row_pass(plane + rowoff[0], x4, xq, seg, h0, d);
#pragma unroll
    for (int c = 0; c < VEC; ++c) { gx[c] = d[c]; b[c] = h0[c]; }
    row_pass(plane + rowoff[1], x4, xq, seg, h, d);
#pragma unroll
    for (int c = 0; c < VEC; ++c) { gx[c] += d[c]; b[c] += h[c]; }
    row_pass(plane + rowoff[2], x4, xq, seg, h, d);
#pragma unroll
    for (int c = 0; c < VEC; ++c) {
        gx[c] += d[c]; b[c] += h[c]; gy[c] = h[c] - h0[c];
    }
}

// One z-step: produce stats for plane z0+kk+1 into slot s2, then emit output
// plane z0+kk from slots (s0 = z-1, s1 = z, s2 = z+1).
#define STEP(s0, s1, s2, kk)                                                  \
    {                                                                         \
        int zq = z0 + (kk) + 1;                                               \
        int gz = zq > NZ - 1 ? NZ - 1 : zq;                                   \
        plane_pass(I + (size_t)gz * NXY, rowoff, x4, xq, seg,                 \
                   gxI[s2], gyI[s2], bI[s2]);                                 \
        plane_pass(J + (size_t)gz * NXY, rowoff, x4, xq, seg,                 \
                   gxJ[s2], gyJ[s2], bJ[s2]);                                 \
        float4 m4 = *reinterpret_cast<const float4*>(mp);                     \
        const float mm[VEC] = {m4.x, m4.y, m4.z, m4.w};                       \
        _Pragma("unroll")                                                     \
        for (int c = 0; c < VEC; ++c) {                                       \
            float Ix = gxI[s0][c] + gxI[s1][c] + gxI[s2][c];                  \
            float Iy = gyI[s0][c] + gyI[s1][c] + gyI[s2][c];                  \
            float Iz = bI[s2][c] - bI[s0][c];                                 \
            float Jx = gxJ[s0][c] + gxJ[s1][c] + gxJ[s2][c];                  \
            float Jy = gyJ[s0][c] + gyJ[s1][c] + gyJ[s2][c];                  \
            float Jz = bJ[s2][c] - bJ[s0][c];                                 \
            float ssi  = fmaf(Ix, Ix, fmaf(Iy, Iy, Iz * Iz));                 \
            float ssj  = fmaf(Jx, Jx, fmaf(Jy, Jy, Jz * Jz));                 \
            float sdot = fmaf(Ix, Jx, fmaf(Iy, Jy, Iz * Jz));                 \
            float imag = fmaf(0.25f, ssi, 0.01f);  /* 0.25*ssi + EPS^2 */     \
            float jmag = fmaf(0.25f, ssj, 0.01f);                             \
            float ngf  = __fdividef(0.0625f * sdot * sdot, imag * jmag);      \
            acc = fmaf(1.0f - ngf, mm[c], acc);                               \
        }                                                                     \
        mp += NXY;                                                            \
    }

__global__ __launch_bounds__(NTHREADS, 4)
void ngf_kernel(const float* __restrict__ I,
                const float* __restrict__ J,
                const float* __restrict__ M,
                float* __restrict__ out)
{
    __shared__ float warp_sums[WYD];

    const int lane = threadIdx.x;
    const int wy   = threadIdx.y;
    const int tid  = wy * 32 + lane;
    const int xq   = lane & (XLANES - 1);
    const int ys   = lane >> 4;
    const int seg  = blockIdx.x;
    const int x4   = seg * SEGW + xq * VEC;
    const int y    = blockIdx.y * (WYD * YSPW) + wy * YSPW + ys;
    const int z0   = blockIdx.z * ZCHUNK;

    // Clamped y row offsets (y-1, y, y+1), constant across z
    int rowoff[3];
#pragma unroll
    for (int r = 0; r < 3; ++r) {
        int gy = y - 1 + r;
        gy = gy < 0 ? 0 : (gy > NY - 1 ? NY - 1 : gy);
        rowoff[r] = gy * NX;
    }

    // Rotating per-plane stats (slot = one z-plane), 4 voxels per thread
    float gxI[3][VEC], gyI[3][VEC], bI[3][VEC];
    float gxJ[3][VEC], gyJ[3][VEC], bJ[3][VEC];

    // Prologue: plane z0-1 (clamped) -> slot 0, plane z0 -> slot 1
    {
        int gzm = z0 - 1 < 0 ? 0 : z0 - 1;
        plane_pass(I + (size_t)gzm * NXY, rowoff, x4, xq, seg, gxI[0], gyI[0], bI[0]);
        plane_pass(J + (size_t)gzm * NXY, rowoff, x4, xq, seg, gxJ[0], gyJ[0], bJ[0]);
        plane_pass(I + (size_t)z0  * NXY, rowoff, x4, xq, seg, gxI[1], gyI[1], bI[1]);
        plane_pass(J + (size_t)z0  * NXY, rowoff, x4, xq, seg, gxJ[1], gyJ[1], bJ[1]);
    }

    float acc = 0.0f;
    const float* mp = M + (size_t)z0 * NXY + (size_t)y * NX + x4;

    // ZCHUNK = 24 steps as 8 x 3-unrolled groups (static slot phase)
    for (int kb = 0; kb < ZCHUNK; kb += 3) {
        STEP(0, 1, 2, kb + 0)
        STEP(1, 2, 0, kb + 1)
        STEP(2, 0, 1, kb + 2)
    }

    // Block reduction
#pragma unroll
    for (int off = 16; off > 0; off >>= 1)
        acc += __shfl_xor_sync(FULLMASK, acc, off);
    if (lane == 0) warp_sums[wy] = acc;
    __syncthreads();

    if (tid == 0) {
        float v = warp_sums[0] + warp_sums[1] + warp_sums[2] + warp_sums[3];
        atomicAdd(&g_acc, (double)v);
        __threadfence();
        unsigned prev = atomicAdd(&g_done, 1u);
        if (prev == NBLOCKS - 1) {
            // All other blocks' g_acc adds are fenced before their g_done
            // increments, so an atomic read here sees the full sum.
            double tot = atomicAdd(&g_acc, 0.0);
            out[0] = (float)(tot * (1.0 / (double)((long long)NX * NY * NZ)));
            g_acc = 0.0;       // reset for next replay (deterministic)
            __threadfence();
            g_done = 0;
        }
    }
}

extern "C" void kernel_launch(void* const* d_in, const int* in_sizes, int n_in,
                              void* d_out, int out_size) {
    const float* I = (const float*)d_in[0];
    const float* J = (const float*)d_in[1];
    const float* M = (const float*)d_in[2];
    float* out = (float*)d_out;

    dim3 block(32, WYD, 1);
    dim3 grid(GXB, GYB, GZB);   // 3 x 24 x 8 = 576 CTAs, single wave at 4/SM
    ngf_kernel<<<grid, block>>>(I, J, M, out);
}

// round 6
// speedup vs baseline: 1.7901x; 1.7901x over previous
#include <cuda_runtime.h>
#include <cuda_bf16.h>

#define NX 192
#define NY 192
#define NZ 192
#define NXY (NX * NY)

#define VEC 2                    // float2 per thread in x
#define SEGW (32 * VEC)          // 64 x per warp
#define WYD 4                    // 4 warps/CTA, 1 y-row each
#define NTHREADS 128
#define ZCHUNK 32                // even (2-phase slot rotation)
#define GXB (NX / SEGW)          // 3
#define GYB (NY / WYD)           // 48
#define GZB (NZ / ZCHUNK)        // 6
#define NBLOCKS (GXB * GYB * GZB) // 864 (single wave at 6 CTAs/SM)

#define FULLMASK 0xFFFFFFFFu

__device__ double g_acc = 0.0;
__device__ unsigned int g_done = 0;

// One image plane, this thread's float2 at (x2, y): compute per-element
//   gx = sum_{dy in -1..1} [v(x+1)-v(x-1)]
//   gy = rowsum(y+1) - rowsum(y-1)
//   b  = 3x3 box sum
// x-neighbors via lane shuffles (segment-edge lanes patch from memory).
__device__ __forceinline__ void plane_pass(
    const float* __restrict__ base, const int* __restrict__ co,
    int lane, int segL, int segR,
    float& gx0, float& gx1, float& gy0, float& gy1, float& b0, float& b1)
{
    float h0[3], h1[3], d0s = 0.f, d1s = 0.f;
#pragma unroll
    for (int r = 0; r < 3; ++r) {
        const float* p = base + co[r];
        float2 v = *reinterpret_cast<const float2*>(p);
        float l = __shfl_up_sync(FULLMASK, v.y, 1);
        float rr = __shfl_down_sync(FULLMASK, v.x, 1);
        if (lane == 0)  l  = segL ? v.x : p[-1];
        if (lane == 31) rr = segR ? v.y : p[2];
        float s = v.x + v.y;
        h0[r] = l + s;
        h1[r] = s + rr;
        d0s += v.y - l;
        d1s += rr - v.x;
    }
    gx0 = d0s;
    gx1 = d1s;
    gy0 = h0[2] - h0[0];
    gy1 = h1[2] - h1[0];
    b0  = h0[0] + h0[1] + h0[2];
    b1  = h1[0] + h1[1] + h1[2];
}

// One z-step for output plane z0+kk. Slot `o` = stats(z-1), slot `m` = stats(z).
// Fresh stats(z+1) computed into temporaries, then written over slot `o`.
#define STEP(o, m, kk)                                                        \
    {                                                                         \
        int zq = z0 + (kk) + 1;                                               \
        int gz = zq > NZ - 1 ? NZ - 1 : zq;                                   \
        float ngxI0, ngxI1, ngyI0, ngyI1, nbI0, nbI1;                         \
        float ngxJ0, ngxJ1, ngyJ0, ngyJ1, nbJ0, nbJ1;                         \
        plane_pass(I + (size_t)gz * NXY, co, lane, segL, segR,                \
                   ngxI0, ngxI1, ngyI0, ngyI1, nbI0, nbI1);                   \
        plane_pass(J + (size_t)gz * NXY, co, lane, segL, segR,                \
                   ngxJ0, ngxJ1, ngyJ0, ngyJ1, nbJ0, nbJ1);                   \
        float2 m2 = *reinterpret_cast<const float2*>(mp);                     \
        {                                                                     \
            float Ix = gxI[o][0] + gxI[m][0] + ngxI0;                         \
            float Iy = gyI[o][0] + gyI[m][0] + ngyI0;                         \
            float Iz = nbI0 - bI[o][0];                                       \
            float Jx = gxJ[o][0] + gxJ[m][0] + ngxJ0;                         \
            float Jy = gyJ[o][0] + gyJ[m][0] + ngyJ0;                         \
            float Jz = nbJ0 - bJ[o][0];                                       \
            float ssi  = fmaf(Ix, Ix, fmaf(Iy, Iy, Iz * Iz));                 \
            float ssj  = fmaf(Jx, Jx, fmaf(Jy, Jy, Jz * Jz));                 \
            float sdot = fmaf(Ix, Jx, fmaf(Iy, Jy, Iz * Jz));                 \
            float imag = fmaf(0.25f, ssi, 0.01f);                             \
            float jmag = fmaf(0.25f, ssj, 0.01f);                             \
            float ngf  = __fdividef(0.0625f * sdot * sdot, imag * jmag);      \
            acc = fmaf(1.0f - ngf, m2.x, acc);                                \
        }                                                                     \
        {                                                                     \
            float Ix = gxI[o][1] + gxI[m][1] + ngxI1;                         \
            float Iy = gyI[o][1] + gyI[m][1] + ngyI1;                         \
            float Iz = nbI1 - bI[o][1];                                       \
            float Jx = gxJ[o][1] + gxJ[m][1] + ngxJ1;                         \
            float Jy = gyJ[o][1] + gyJ[m][1] + ngyJ1;                         \
            float Jz = nbJ1 - bJ[o][1];                                       \
            float ssi  = fmaf(Ix, Ix, fmaf(Iy, Iy, Iz * Iz));                 \
            float ssj  = fmaf(Jx, Jx, fmaf(Jy, Jy, Jz * Jz));                 \
            float sdot = fmaf(Ix, Jx, fmaf(Iy, Jy, Iz * Jz));                 \
            float imag = fmaf(0.25f, ssi, 0.01f);                             \
            float jmag = fmaf(0.25f, ssj, 0.01f);                             \
            float ngf  = __fdividef(0.0625f * sdot * sdot, imag * jmag);      \
            acc = fmaf(1.0f - ngf, m2.y, acc);                                \
        }                                                                     \
        gxI[o][0] = ngxI0; gxI[o][1] = ngxI1;                                 \
        gyI[o][0] = ngyI0; gyI[o][1] = ngyI1;                                 \
        bI[o][0]  = nbI0;  bI[o][1]  = nbI1;                                  \
        gxJ[o][0] = ngxJ0; gxJ[o][1] = ngxJ1;                                 \
        gyJ[o][0] = ngyJ0; gyJ[o][1] = ngyJ1;                                 \
        bJ[o][0]  = nbJ0;  bJ[o][1]  = nbJ1;                                  \
        mp += NXY;                                                            \
    }

__global__ __launch_bounds__(NTHREADS, 6)
void ngf_kernel(const float* __restrict__ I,
                const float* __restrict__ J,
                const float* __restrict__ M,
                float* __restrict__ out)
{
    __shared__ float warp_sums[WYD];

    const int lane = threadIdx.x;
    const int wy   = threadIdx.y;
    const int tid  = wy * 32 + lane;
    const int seg  = blockIdx.x;
    const int x2   = seg * SEGW + lane * VEC;
    const int y    = blockIdx.y * WYD + wy;
    const int z0   = blockIdx.z * ZCHUNK;
    const int segL = (seg == 0);
    const int segR = (seg == GXB - 1);

    // Combined (clamped y-row + x) element offsets, constant across z
    int co[3];
#pragma unroll
    for (int r = 0; r < 3; ++r) {
        int gy = y - 1 + r;
        gy = gy < 0 ? 0 : (gy > NY - 1 ? NY - 1 : gy);
        co[r] = gy * NX + x2;
    }

    // 2-slot rolling z-state: [0]/[1] alternate as (z-1)/(z) per step phase
    float gxI[2][VEC], gyI[2][VEC], bI[2][VEC];
    float gxJ[2][VEC], gyJ[2][VEC], bJ[2][VEC];

    // Prologue: plane z0-1 (clamped) -> slot 0, plane z0 -> slot 1
    {
        int gzm = z0 - 1 < 0 ? 0 : z0 - 1;
        plane_pass(I + (size_t)gzm * NXY, co, lane, segL, segR,
                   gxI[0][0], gxI[0][1], gyI[0][0], gyI[0][1], bI[0][0], bI[0][1]);
        plane_pass(J + (size_t)gzm * NXY, co, lane, segL, segR,
                   gxJ[0][0], gxJ[0][1], gyJ[0][0], gyJ[0][1], bJ[0][0], bJ[0][1]);
        plane_pass(I + (size_t)z0 * NXY, co, lane, segL, segR,
                   gxI[1][0], gxI[1][1], gyI[1][0], gyI[1][1], bI[1][0], bI[1][1]);
        plane_pass(J + (size_t)z0 * NXY, co, lane, segL, segR,
                   gxJ[1][0], gxJ[1][1], gyJ[1][0], gyJ[1][1], bJ[1][0], bJ[1][1]);
    }

    float acc = 0.0f;
    const float* mp = M + (size_t)z0 * NXY + co[1];  // co[1] == y*NX + x2

    // ZCHUNK steps, 2-phase unrolled: slots alternate (0,1) -> (1,0)
    for (int kb = 0; kb < ZCHUNK; kb += 2) {
        STEP(0, 1, kb + 0)
        STEP(1, 0, kb + 1)
    }

    // Block reduction
#pragma unroll
    for (int off = 16; off > 0; off >>= 1)
        acc += __shfl_xor_sync(FULLMASK, acc, off);
    if (lane == 0) warp_sums[wy] = acc;
    __syncthreads();

    if (tid == 0) {
        float v = warp_sums[0] + warp_sums[1] + warp_sums[2] + warp_sums[3];
        atomicAdd(&g_acc, (double)v);
        __threadfence();
        unsigned prev = atomicAdd(&g_done, 1u);
        if (prev == NBLOCKS - 1) {
            // All other blocks' g_acc adds are fenced before their g_done
            // increments, so an atomic read here sees the full sum.
            double tot = atomicAdd(&g_acc, 0.0);
            out[0] = (float)(tot * (1.0 / (double)((long long)NX * NY * NZ)));
            g_acc = 0.0;       // reset for next replay (deterministic)
            __threadfence();
            g_done = 0;
        }
    }
}

extern "C" void kernel_launch(void* const* d_in, const int* in_sizes, int n_in,
                              void* d_out, int out_size) {
    const float* I = (const float*)d_in[0];
    const float* J = (const float*)d_in[1];
    const float* M = (const float*)d_in[2];
    float* out = (float*)d_out;

    dim3 block(32, WYD, 1);
    dim3 grid(GXB, GYB, GZB);   // 3 x 48 x 6 = 864 CTAs
    ngf_kernel<<<grid, block>>>(I, J, M, out);
}